// round 2
// baseline (speedup 1.0000x reference)
#include <cuda_runtime.h>

// ---------------------------------------------------------------------------
// B6Model: BN -> TAGConv(67->128,K=3) -> BN -> LeakyReLU -> TAGConv(128->1,K=3)
//
// Strategy:
//  * CSR-by-target built per launch (deterministic, no float atomics)
//  * layer1: propagate in 67-dim space (3 hops, warp-per-node gather-sum),
//            then ONE fused GEMM  [N, 4*68] x [272, 128]  with all weights
//            resident in shared memory.
//  * layer2: A and W commute; DOUT=1 => Horner on per-node scalars:
//            out = t0 + A(t1 + A(t2 + A t3)),  tk = h2 . W2[k]
// ---------------------------------------------------------------------------

#define N_NODES 100000
#define N_EDGES 1600000
#define DIN     67
#define DH      128
#define EPSBN   1e-5f
#define SLOPE   0.01f
#define DPAD    68          // 67 padded to 68 (pad column held at 0)
#define DCAT    272         // 4 * DPAD
#define HSTRIDE 288         // row stride of hcat in floats (1152B, 16B-multiple)

// ------------------------------ scratch (no allocations allowed) -----------
// NOTE: every array touched with float4 is explicitly 16B-aligned; a plain
// __device__ float array only guarantees 4B alignment -> LDG.128 would trap.
__device__ int    g_cnt[N_NODES];
__device__ int    g_cnt2[N_NODES];
__device__ int    g_indptr[N_NODES + 1];
__device__ float  g_dis[N_NODES];
__device__ int    g_src[N_EDGES];
__device__ float  g_ew[N_EDGES];
__device__ __align__(16) float g_hcat[(size_t)N_NODES * HSTRIDE]; // [N][288]
__device__ __align__(16) float g_out1[(size_t)N_NODES * DH];      // [N,128]
__device__ __align__(16) float4 g_W4[DCAT * 32];  // Wcat^T, float4 over channels
__device__ float  g_t[4 * N_NODES];               // t0..t3 scalars
__device__ float  g_u[2 * N_NODES];               // Horner ping-pong

// ------------------------------ CSR construction ---------------------------
__global__ void k_zero() {
    int i = blockIdx.x * blockDim.x + threadIdx.x;
    if (i < N_NODES) { g_cnt[i] = 0; g_cnt2[i] = 0; }
}

__global__ void k_count(const int* __restrict__ col) {
    int e = blockIdx.x * blockDim.x + threadIdx.x;
    if (e < N_EDGES) atomicAdd(&g_cnt[col[e]], 1);
}

__global__ void k_dis() {
    int i = blockIdx.x * blockDim.x + threadIdx.x;
    if (i < N_NODES) {
        int c = g_cnt[i];
        g_dis[i] = (c > 0) ? rsqrtf((float)c) : 0.0f;
    }
}

// single-block exclusive scan of g_cnt -> g_indptr  (N=100k, 1024 threads)
__global__ void k_scan() {
    __shared__ int sums[1024];
    const int C = (N_NODES + 1023) / 1024;   // 98
    int t = threadIdx.x;
    int lo = t * C;
    int hi = lo + C; if (hi > N_NODES) hi = N_NODES;
    int s = 0;
    for (int i = lo; i < hi; ++i) s += g_cnt[i];
    sums[t] = s;
    __syncthreads();
    // Hillis-Steele inclusive scan (two-sync, no double buffer needed)
    for (int off = 1; off < 1024; off <<= 1) {
        int v = (t >= off) ? sums[t - off] : 0;
        __syncthreads();
        sums[t] += v;
        __syncthreads();
    }
    int run = (t == 0) ? 0 : sums[t - 1];
    for (int i = lo; i < hi; ++i) {
        g_indptr[i] = run;
        run += g_cnt[i];
    }
    if (t == 1023) g_indptr[N_NODES] = sums[1023];
}

__global__ void k_fill(const int* __restrict__ row, const int* __restrict__ col) {
    int e = blockIdx.x * blockDim.x + threadIdx.x;
    if (e >= N_EDGES) return;
    int c = col[e];
    int r = row[e];
    int p = g_indptr[c] + atomicAdd(&g_cnt2[c], 1);
    g_src[p] = r;
    g_ew[p]  = g_dis[r] * g_dis[c];
}

// ------------------------------ weight prep --------------------------------
// g_W4[d*32 + tc] = { Wcat[tc*4+0][d], ..., Wcat[tc*4+3][d] },  d = k*68 + dd
__global__ void k_prepw(const float* __restrict__ W1) {
    int i = blockIdx.x * blockDim.x + threadIdx.x;
    if (i >= DCAT * 32) return;
    int d  = i >> 5;
    int tc = i & 31;
    int k  = d / DPAD;
    int dd = d - k * DPAD;
    float4 v;
    if (dd < DIN) {
        const float* w = &W1[(size_t)k * DH * DIN + (size_t)(tc * 4) * DIN + dd];
        v.x = w[0 * DIN];
        v.y = w[1 * DIN];
        v.z = w[2 * DIN];
        v.w = w[3 * DIN];
    } else {
        v = make_float4(0.f, 0.f, 0.f, 0.f);
    }
    g_W4[i] = v;
}

// ------------------------------ BN1 -> hcat slice 0 ------------------------
__global__ void k_bn1(const float* __restrict__ x,
                      const float* __restrict__ g1, const float* __restrict__ b1,
                      const float* __restrict__ m1, const float* __restrict__ v1) {
    int i = blockIdx.x * blockDim.x + threadIdx.x;
    if (i >= N_NODES * DPAD) return;
    int n = i / DPAD;
    int d = i - n * DPAD;
    float val = 0.0f;
    if (d < DIN) {
        float xv = x[(size_t)n * DIN + d];
        val = (xv - m1[d]) * rsqrtf(v1[d] + EPSBN) * g1[d] + b1[d];
    }
    g_hcat[(size_t)n * HSTRIDE + d] = val;
}

// ------------------------------ hop propagation (67-dim) -------------------
// warp per target node; lanes stripe feature row (68 floats, pad stays 0)
__global__ void k_prop(int srcOff, int dstOff) {
    int gid  = blockIdx.x * blockDim.x + threadIdx.x;
    int node = gid >> 5;
    int lane = gid & 31;
    if (node >= N_NODES) return;
    int s = g_indptr[node];
    int e = g_indptr[node + 1];
    float a0 = 0.f, a1 = 0.f, a2 = 0.f;
    for (int i = s; i < e; ++i) {
        int   src = __ldg(&g_src[i]);            // uniform -> broadcast
        float w   = __ldg(&g_ew[i]);
        const float* hp = &g_hcat[(size_t)src * HSTRIDE + srcOff];
        a0 += w * __ldg(&hp[lane]);
        a1 += w * __ldg(&hp[lane + 32]);
        if (lane < 4) a2 += w * __ldg(&hp[lane + 64]);
    }
    float* op = &g_hcat[(size_t)node * HSTRIDE + dstOff];
    op[lane]      = a0;
    op[lane + 32] = a1;
    if (lane < 4) op[lane + 64] = a2;
}

// ------------------------------ fused GEMM [N,272] x [272,128] -------------
// block: 256 threads, 64 nodes x 128 channels; thread: 4 channels x 8 nodes.
// Shared: Wcat (139.3KB, float4 over channel groups) + h-tile transposed (69.6KB)
// Total 208,896 B dynamic smem (< 227KB sm_100a cap), occupancy 1 CTA/SM.
#define GEMM_SMEM_BYTES ((DCAT * DH + DCAT * 64) * 4)

__global__ void __launch_bounds__(256, 1) k_gemm(const float* __restrict__ bias1) {
    extern __shared__ __align__(16) float sm[];
    float4* Ws4 = (float4*)sm;               // [DCAT][32] float4
    float*  hsT = sm + DCAT * DH;            // [DCAT][64]
    int tid   = threadIdx.x;
    int nbase = blockIdx.x * 64;

    for (int i = tid; i < DCAT * 32; i += 256)
        Ws4[i] = g_W4[i];

    for (int idx = tid; idx < 64 * DPAD; idx += 256) {
        int n  = idx & 63;
        int d4 = idx >> 6;                    // 0..67 -> floats d4*4 .. d4*4+3
        int ng = nbase + n;
        float4 v = make_float4(0.f, 0.f, 0.f, 0.f);
        if (ng < N_NODES)
            v = *(const float4*)&g_hcat[(size_t)ng * HSTRIDE + d4 * 4];
        hsT[(d4 * 4 + 0) * 64 + n] = v.x;
        hsT[(d4 * 4 + 1) * 64 + n] = v.y;
        hsT[(d4 * 4 + 2) * 64 + n] = v.z;
        hsT[(d4 * 4 + 3) * 64 + n] = v.w;
    }
    __syncthreads();

    int tc = tid & 31;     // channel group (lane) -> channels tc*4..tc*4+3
    int tn = tid >> 5;     // node group (warp)    -> nodes  nbase+tn*8..+7

    float acc[4][8];
#pragma unroll
    for (int j = 0; j < 4; ++j)
#pragma unroll
        for (int i = 0; i < 8; ++i) acc[j][i] = 0.f;

#pragma unroll 4
    for (int d = 0; d < DCAT; ++d) {
        float4 w = Ws4[d * 32 + tc];                       // lane-consecutive LDS.128
        const float* hrow = &hsT[d * 64 + tn * 8];         // warp-broadcast LDS.128
        float4 h0 = *(const float4*)hrow;
        float4 h1 = *(const float4*)(hrow + 4);
        float hv[8] = {h0.x, h0.y, h0.z, h0.w, h1.x, h1.y, h1.z, h1.w};
#pragma unroll
        for (int i = 0; i < 8; ++i) {
            acc[0][i] += w.x * hv[i];
            acc[1][i] += w.y * hv[i];
            acc[2][i] += w.z * hv[i];
            acc[3][i] += w.w * hv[i];
        }
    }

    float4 b4 = *(const float4*)&bias1[tc * 4];
#pragma unroll
    for (int i = 0; i < 8; ++i) {
        int n = nbase + tn * 8 + i;
        if (n < N_NODES) {
            float4 o;
            o.x = acc[0][i] + b4.x;
            o.y = acc[1][i] + b4.y;
            o.z = acc[2][i] + b4.z;
            o.w = acc[3][i] + b4.w;
            *(float4*)&g_out1[(size_t)n * DH + tc * 4] = o;
        }
    }
}

// ------------------------------ BN2 + leakyrelu + 4 dot products -----------
__global__ void k_bn2dot(const float* __restrict__ g2, const float* __restrict__ b2,
                         const float* __restrict__ m2, const float* __restrict__ v2,
                         const float* __restrict__ W2) {
    int gid  = blockIdx.x * blockDim.x + threadIdx.x;
    int node = gid >> 5;
    int lane = gid & 31;
    if (node >= N_NODES) return;

    float4 h  = *(const float4*)&g_out1[(size_t)node * DH + lane * 4];
    float4 gg = *(const float4*)&g2[lane * 4];
    float4 bb = *(const float4*)&b2[lane * 4];
    float4 mm = *(const float4*)&m2[lane * 4];
    float4 vv = *(const float4*)&v2[lane * 4];

    h.x = (h.x - mm.x) * rsqrtf(vv.x + EPSBN) * gg.x + bb.x;
    h.y = (h.y - mm.y) * rsqrtf(vv.y + EPSBN) * gg.y + bb.y;
    h.z = (h.z - mm.z) * rsqrtf(vv.z + EPSBN) * gg.z + bb.z;
    h.w = (h.w - mm.w) * rsqrtf(vv.w + EPSBN) * gg.w + bb.w;
    h.x = (h.x > 0.f) ? h.x : SLOPE * h.x;
    h.y = (h.y > 0.f) ? h.y : SLOPE * h.y;
    h.z = (h.z > 0.f) ? h.z : SLOPE * h.z;
    h.w = (h.w > 0.f) ? h.w : SLOPE * h.w;

    float t[4];
#pragma unroll
    for (int k = 0; k < 4; ++k) {
        float4 w = *(const float4*)&W2[k * DH + lane * 4];
        t[k] = w.x * h.x + w.y * h.y + w.z * h.z + w.w * h.w;
    }
#pragma unroll
    for (int off = 16; off; off >>= 1) {
#pragma unroll
        for (int k = 0; k < 4; ++k)
            t[k] += __shfl_xor_sync(0xffffffff, t[k], off);
    }
    if (lane == 0) {
        g_t[0 * N_NODES + node] = t[0];
        g_t[1 * N_NODES + node] = t[1];
        g_t[2 * N_NODES + node] = t[2];
        g_t[3 * N_NODES + node] = t[3];
    }
}

// ------------------------------ scalar Horner propagation ------------------
// phase 0: u0 = t2 + A t3 ; phase 1: u1 = t1 + A u0 ; phase 2: out = t0 + A u1 + bias2
__global__ void k_sprop(int phase, const float* __restrict__ bias2,
                        float* __restrict__ dout) {
    int n = blockIdx.x * blockDim.x + threadIdx.x;
    if (n >= N_NODES) return;
    const float* prev;
    const float* tk;
    if (phase == 0)      { prev = &g_t[3 * N_NODES]; tk = &g_t[2 * N_NODES]; }
    else if (phase == 1) { prev = &g_u[0];           tk = &g_t[1 * N_NODES]; }
    else                 { prev = &g_u[N_NODES];     tk = &g_t[0]; }

    float a = tk[n];
    int s = g_indptr[n], e = g_indptr[n + 1];
    for (int i = s; i < e; ++i)
        a += __ldg(&g_ew[i]) * __ldg(&prev[g_src[i]]);

    if (phase == 0)      g_u[n] = a;
    else if (phase == 1) g_u[N_NODES + n] = a;
    else                 dout[n] = a + bias2[0];
}

// ---------------------------------------------------------------------------
extern "C" void kernel_launch(void* const* d_in, const int* in_sizes, int n_in,
                              void* d_out, int out_size) {
    const float* x     = (const float*)d_in[0];
    const int*   ei    = (const int*)  d_in[1];
    const float* g1    = (const float*)d_in[2];
    const float* b1    = (const float*)d_in[3];
    const float* m1    = (const float*)d_in[4];
    const float* v1    = (const float*)d_in[5];
    const float* W1    = (const float*)d_in[6];
    const float* bias1 = (const float*)d_in[7];
    const float* g2    = (const float*)d_in[8];
    const float* b2    = (const float*)d_in[9];
    const float* m2    = (const float*)d_in[10];
    const float* v2    = (const float*)d_in[11];
    const float* W2    = (const float*)d_in[12];
    const float* bias2 = (const float*)d_in[13];
    const int* row = ei;
    const int* col = ei + N_EDGES;
    float* out = (float*)d_out;

    cudaFuncSetAttribute(k_gemm, cudaFuncAttributeMaxDynamicSharedMemorySize,
                         GEMM_SMEM_BYTES);

    const int TB = 256;
    // ---- CSR build ----
    k_zero <<<(N_NODES + TB - 1) / TB, TB>>>();
    k_count<<<(N_EDGES + TB - 1) / TB, TB>>>(col);
    k_dis  <<<(N_NODES + TB - 1) / TB, TB>>>();
    k_scan <<<1, 1024>>>();
    k_fill <<<(N_EDGES + TB - 1) / TB, TB>>>(row, col);

    // ---- weights + BN1 ----
    k_prepw<<<(DCAT * 32 + TB - 1) / TB, TB>>>(W1);
    k_bn1  <<<(N_NODES * DPAD + TB - 1) / TB, TB>>>(x, g1, b1, m1, v1);

    // ---- layer1: 3 propagation hops in 67-dim space ----
    int propGrid = (N_NODES * 32 + TB - 1) / TB;
    k_prop<<<propGrid, TB>>>(0 * DPAD, 1 * DPAD);
    k_prop<<<propGrid, TB>>>(1 * DPAD, 2 * DPAD);
    k_prop<<<propGrid, TB>>>(2 * DPAD, 3 * DPAD);

    // ---- layer1: fused projection GEMM ----
    k_gemm<<<(N_NODES + 63) / 64, 256, GEMM_SMEM_BYTES>>>(bias1);

    // ---- layer2: BN2 + leakyrelu + scalar projections ----
    k_bn2dot<<<(N_NODES * 32 + TB - 1) / TB, TB>>>(g2, b2, m2, v2, W2);

    // ---- layer2: Horner scalar propagation ----
    int ng = (N_NODES + TB - 1) / TB;
    k_sprop<<<ng, TB>>>(0, bias2, out);
    k_sprop<<<ng, TB>>>(1, bias2, out);
    k_sprop<<<ng, TB>>>(2, bias2, out);
}

// round 4
// speedup vs baseline: 1.2166x; 1.2166x over previous
#include <cuda_runtime.h>

// ---------------------------------------------------------------------------
// B6Model: BN -> TAGConv(67->128,K=3) -> BN -> LeakyReLU -> TAGConv(128->1,K=3)
//
//  * CSR-by-target built per launch; hierarchical 3-kernel scan
//  * layer1: propagate in 67-dim space (3 hops, warp-per-node gather, 2-way
//    unrolled for MLP), then ONE fused GEMM [N,272] x [272,128] with all
//    weights shared-resident, inner loop in packed fma.rn.f32x2 (FFMA2,
//    guarded by __CUDA_ARCH__ with scalar fallback).
//  * layer2: A/W commute; DOUT=1 => Horner on per-node scalars.
// ---------------------------------------------------------------------------

#define N_NODES 100000
#define N_EDGES 1600000
#define DIN     67
#define DH      128
#define EPSBN   1e-5f
#define SLOPE   0.01f
#define DPAD    68
#define DCAT    272
#define HSTRIDE 288

#define SCAN_B   512
#define SCAN_NB  ((N_NODES + SCAN_B - 1) / SCAN_B)   // 196

// ------------------------------ scratch ------------------------------------
__device__ int    g_cnt[N_NODES];
__device__ int    g_cnt2[N_NODES];
__device__ int    g_indptr[N_NODES + 1];
__device__ int    g_bsum[256];
__device__ int    g_boff[256];
__device__ float  g_dis[N_NODES];
__device__ int    g_src[N_EDGES];
__device__ float  g_ew[N_EDGES];
__device__ __align__(16) float g_hcat[(size_t)N_NODES * HSTRIDE]; // [N][288]
__device__ __align__(16) float g_out1[(size_t)N_NODES * DH];      // [N,128]
__device__ __align__(16) float4 g_W4[DCAT * 32];  // Wcat^T, float4 over channels
__device__ float  g_t[4 * N_NODES];
__device__ float  g_u[2 * N_NODES];

#if defined(__CUDA_ARCH__) && (__CUDA_ARCH__ >= 1000)
#define HAVE_F32X2 1
#else
#define HAVE_F32X2 0
#endif

// packed f32x2 helpers (Blackwell FFMA2 path)
#define PACKF2(out, lo, hi) \
    asm("mov.b64 %0, {%1, %2};" : "=l"(out) : "r"(__float_as_uint(lo)), "r"(__float_as_uint(hi)))
#define UNPACKF2(lo, hi, in) \
    do { unsigned int _a, _b; \
         asm("mov.b64 {%0, %1}, %2;" : "=r"(_a), "=r"(_b) : "l"(in)); \
         lo = __uint_as_float(_a); hi = __uint_as_float(_b); } while (0)
#define FMAF2(acc, a, b) \
    asm("fma.rn.f32x2 %0, %1, %2, %0;" : "+l"(acc) : "l"(a), "l"(b))

// ------------------------------ CSR construction ---------------------------
__global__ void k_zero() {
    int i = blockIdx.x * blockDim.x + threadIdx.x;
    if (i < N_NODES) { g_cnt[i] = 0; g_cnt2[i] = 0; }
}

__global__ void k_count(const int* __restrict__ col) {
    int e = blockIdx.x * blockDim.x + threadIdx.x;
    if (e < N_EDGES) atomicAdd(&g_cnt[col[e]], 1);
}

__global__ void k_dis() {
    int i = blockIdx.x * blockDim.x + threadIdx.x;
    if (i < N_NODES) {
        int c = g_cnt[i];
        g_dis[i] = (c > 0) ? rsqrtf((float)c) : 0.0f;
    }
}

// hierarchical scan: per-block exclusive scan + block sums
__global__ void k_scan1() {
    __shared__ int sh[SCAN_B];
    int t = threadIdx.x;
    int i = blockIdx.x * SCAN_B + t;
    int v = (i < N_NODES) ? g_cnt[i] : 0;
    sh[t] = v;
    __syncthreads();
    for (int off = 1; off < SCAN_B; off <<= 1) {
        int u = (t >= off) ? sh[t - off] : 0;
        __syncthreads();
        sh[t] += u;
        __syncthreads();
    }
    if (i < N_NODES) g_indptr[i] = sh[t] - v;      // local exclusive
    if (t == SCAN_B - 1) g_bsum[blockIdx.x] = sh[t];
}

// scan of block sums (196 values, one 256-thread block)
__global__ void k_scan2() {
    __shared__ int sh[256];
    int t = threadIdx.x;
    int v = (t < SCAN_NB) ? g_bsum[t] : 0;
    sh[t] = v;
    __syncthreads();
    for (int off = 1; off < 256; off <<= 1) {
        int u = (t >= off) ? sh[t - off] : 0;
        __syncthreads();
        sh[t] += u;
        __syncthreads();
    }
    g_boff[t] = sh[t] - v;                          // exclusive block offset
    if (t == 255) g_indptr[N_NODES] = sh[255];      // total edge count
}

__global__ void k_scan3() {
    int t = threadIdx.x;
    int i = blockIdx.x * SCAN_B + t;
    if (i < N_NODES) g_indptr[i] += g_boff[blockIdx.x];
}

__global__ void k_fill(const int* __restrict__ row, const int* __restrict__ col) {
    int e = blockIdx.x * blockDim.x + threadIdx.x;
    if (e >= N_EDGES) return;
    int c = col[e];
    int r = row[e];
    int p = g_indptr[c] + atomicAdd(&g_cnt2[c], 1);
    g_src[p] = r;
    g_ew[p]  = g_dis[r] * g_dis[c];
}

// ------------------------------ weight prep --------------------------------
__global__ void k_prepw(const float* __restrict__ W1) {
    int i = blockIdx.x * blockDim.x + threadIdx.x;
    if (i >= DCAT * 32) return;
    int d  = i >> 5;
    int tc = i & 31;
    int k  = d / DPAD;
    int dd = d - k * DPAD;
    float4 v;
    if (dd < DIN) {
        const float* w = &W1[(size_t)k * DH * DIN + (size_t)(tc * 4) * DIN + dd];
        v.x = w[0 * DIN];
        v.y = w[1 * DIN];
        v.z = w[2 * DIN];
        v.w = w[3 * DIN];
    } else {
        v = make_float4(0.f, 0.f, 0.f, 0.f);
    }
    g_W4[i] = v;
}

// ------------------------------ BN1 -> hcat slice 0 ------------------------
__global__ void k_bn1(const float* __restrict__ x,
                      const float* __restrict__ g1, const float* __restrict__ b1,
                      const float* __restrict__ m1, const float* __restrict__ v1) {
    int i = blockIdx.x * blockDim.x + threadIdx.x;
    if (i >= N_NODES * DPAD) return;
    int n = i / DPAD;
    int d = i - n * DPAD;
    float val = 0.0f;
    if (d < DIN) {
        float xv = x[(size_t)n * DIN + d];
        val = (xv - m1[d]) * rsqrtf(v1[d] + EPSBN) * g1[d] + b1[d];
    }
    g_hcat[(size_t)n * HSTRIDE + d] = val;
}

// ------------------------------ hop propagation (67-dim) -------------------
// warp per target node, 2-way unrolled edge loop for gather MLP
__global__ void k_prop(int srcOff, int dstOff) {
    int gid  = blockIdx.x * blockDim.x + threadIdx.x;
    int node = gid >> 5;
    int lane = gid & 31;
    if (node >= N_NODES) return;
    int s = g_indptr[node];
    int e = g_indptr[node + 1];
    float a0 = 0.f, a1 = 0.f, a2 = 0.f;
    float b0 = 0.f, b1 = 0.f, b2 = 0.f;
    int i = s;
    for (; i + 1 < e; i += 2) {
        int   s0 = __ldg(&g_src[i]);
        int   s1 = __ldg(&g_src[i + 1]);
        float w0 = __ldg(&g_ew[i]);
        float w1 = __ldg(&g_ew[i + 1]);
        const float* h0 = &g_hcat[(size_t)s0 * HSTRIDE + srcOff];
        const float* h1 = &g_hcat[(size_t)s1 * HSTRIDE + srcOff];
        a0 += w0 * __ldg(&h0[lane]);
        b0 += w1 * __ldg(&h1[lane]);
        a1 += w0 * __ldg(&h0[lane + 32]);
        b1 += w1 * __ldg(&h1[lane + 32]);
        if (lane < 4) {
            a2 += w0 * __ldg(&h0[lane + 64]);
            b2 += w1 * __ldg(&h1[lane + 64]);
        }
    }
    if (i < e) {
        int   s0 = __ldg(&g_src[i]);
        float w0 = __ldg(&g_ew[i]);
        const float* h0 = &g_hcat[(size_t)s0 * HSTRIDE + srcOff];
        a0 += w0 * __ldg(&h0[lane]);
        a1 += w0 * __ldg(&h0[lane + 32]);
        if (lane < 4) a2 += w0 * __ldg(&h0[lane + 64]);
    }
    a0 += b0; a1 += b1; a2 += b2;
    float* op = &g_hcat[(size_t)node * HSTRIDE + dstOff];
    op[lane]      = a0;
    op[lane + 32] = a1;
    if (lane < 4) op[lane + 64] = a2;
}

// ------------------------------ fused GEMM [N,272] x [272,128] -------------
// block: 256 threads, 64 nodes x 128 channels; thread: 4 ch x 8 nodes.
#define GEMM_SMEM_BYTES ((DCAT * DH + DCAT * 64) * 4)

__global__ void __launch_bounds__(256, 1) k_gemm(const float* __restrict__ bias1) {
    extern __shared__ __align__(16) float sm[];
    float4* Ws4 = (float4*)sm;               // [DCAT][32] float4
    float*  hsT = sm + DCAT * DH;            // [DCAT][64]
    int tid   = threadIdx.x;
    int nbase = blockIdx.x * 64;

    for (int i = tid; i < DCAT * 32; i += 256)
        Ws4[i] = g_W4[i];

    for (int idx = tid; idx < 64 * DPAD; idx += 256) {
        int n  = idx & 63;
        int d4 = idx >> 6;
        int ng = nbase + n;
        float4 v = make_float4(0.f, 0.f, 0.f, 0.f);
        if (ng < N_NODES)
            v = *(const float4*)&g_hcat[(size_t)ng * HSTRIDE + d4 * 4];
        hsT[(d4 * 4 + 0) * 64 + n] = v.x;
        hsT[(d4 * 4 + 1) * 64 + n] = v.y;
        hsT[(d4 * 4 + 2) * 64 + n] = v.z;
        hsT[(d4 * 4 + 3) * 64 + n] = v.w;
    }
    __syncthreads();

    int tc = tid & 31;     // channel group -> channels tc*4..tc*4+3
    int tn = tid >> 5;     // node group    -> nodes nbase+tn*8..+7

#if HAVE_F32X2
    unsigned long long acc2[4][4];   // [channel][node-pair]
#pragma unroll
    for (int j = 0; j < 4; ++j)
#pragma unroll
        for (int p = 0; p < 4; ++p) acc2[j][p] = 0ull;

#pragma unroll 4
    for (int d = 0; d < DCAT; ++d) {
        float4 w = Ws4[d * 32 + tc];                        // LDS.128 lane-consecutive
        const unsigned long long* hp =
            (const unsigned long long*)&hsT[d * 64 + tn * 8];
        unsigned long long h01 = hp[0];                     // node pairs (b64 LDS,
        unsigned long long h23 = hp[1];                     //  warp-broadcast)
        unsigned long long h45 = hp[2];
        unsigned long long h67 = hp[3];
        unsigned long long wx, wy, wz, ww;
        PACKF2(wx, w.x, w.x);
        PACKF2(wy, w.y, w.y);
        PACKF2(wz, w.z, w.z);
        PACKF2(ww, w.w, w.w);
        FMAF2(acc2[0][0], wx, h01); FMAF2(acc2[0][1], wx, h23);
        FMAF2(acc2[0][2], wx, h45); FMAF2(acc2[0][3], wx, h67);
        FMAF2(acc2[1][0], wy, h01); FMAF2(acc2[1][1], wy, h23);
        FMAF2(acc2[1][2], wy, h45); FMAF2(acc2[1][3], wy, h67);
        FMAF2(acc2[2][0], wz, h01); FMAF2(acc2[2][1], wz, h23);
        FMAF2(acc2[2][2], wz, h45); FMAF2(acc2[2][3], wz, h67);
        FMAF2(acc2[3][0], ww, h01); FMAF2(acc2[3][1], ww, h23);
        FMAF2(acc2[3][2], ww, h45); FMAF2(acc2[3][3], ww, h67);
    }

    float accf[4][8];
#pragma unroll
    for (int j = 0; j < 4; ++j)
#pragma unroll
        for (int p = 0; p < 4; ++p)
            UNPACKF2(accf[j][2 * p], accf[j][2 * p + 1], acc2[j][p]);
#else
    float accf[4][8];
#pragma unroll
    for (int j = 0; j < 4; ++j)
#pragma unroll
        for (int i = 0; i < 8; ++i) accf[j][i] = 0.f;

#pragma unroll 4
    for (int d = 0; d < DCAT; ++d) {
        float4 w = Ws4[d * 32 + tc];
        const float* hrow = &hsT[d * 64 + tn * 8];
        float4 h0 = *(const float4*)hrow;
        float4 h1 = *(const float4*)(hrow + 4);
        float hv[8] = {h0.x, h0.y, h0.z, h0.w, h1.x, h1.y, h1.z, h1.w};
#pragma unroll
        for (int i = 0; i < 8; ++i) {
            accf[0][i] += w.x * hv[i];
            accf[1][i] += w.y * hv[i];
            accf[2][i] += w.z * hv[i];
            accf[3][i] += w.w * hv[i];
        }
    }
#endif

    float4 b4 = *(const float4*)&bias1[tc * 4];
#pragma unroll
    for (int i = 0; i < 8; ++i) {
        int n = nbase + tn * 8 + i;
        if (n < N_NODES) {
            float4 o;
            o.x = accf[0][i] + b4.x;
            o.y = accf[1][i] + b4.y;
            o.z = accf[2][i] + b4.z;
            o.w = accf[3][i] + b4.w;
            *(float4*)&g_out1[(size_t)n * DH + tc * 4] = o;
        }
    }
}

// ------------------------------ BN2 + leakyrelu + 4 dot products -----------
__global__ void k_bn2dot(const float* __restrict__ g2, const float* __restrict__ b2,
                         const float* __restrict__ m2, const float* __restrict__ v2,
                         const float* __restrict__ W2) {
    int gid  = blockIdx.x * blockDim.x + threadIdx.x;
    int node = gid >> 5;
    int lane = gid & 31;
    if (node >= N_NODES) return;

    float4 h  = *(const float4*)&g_out1[(size_t)node * DH + lane * 4];
    float4 gg = *(const float4*)&g2[lane * 4];
    float4 bb = *(const float4*)&b2[lane * 4];
    float4 mm = *(const float4*)&m2[lane * 4];
    float4 vv = *(const float4*)&v2[lane * 4];

    h.x = (h.x - mm.x) * rsqrtf(vv.x + EPSBN) * gg.x + bb.x;
    h.y = (h.y - mm.y) * rsqrtf(vv.y + EPSBN) * gg.y + bb.y;
    h.z = (h.z - mm.z) * rsqrtf(vv.z + EPSBN) * gg.z + bb.z;
    h.w = (h.w - mm.w) * rsqrtf(vv.w + EPSBN) * gg.w + bb.w;
    h.x = (h.x > 0.f) ? h.x : SLOPE * h.x;
    h.y = (h.y > 0.f) ? h.y : SLOPE * h.y;
    h.z = (h.z > 0.f) ? h.z : SLOPE * h.z;
    h.w = (h.w > 0.f) ? h.w : SLOPE * h.w;

    float t[4];
#pragma unroll
    for (int k = 0; k < 4; ++k) {
        float4 w = *(const float4*)&W2[k * DH + lane * 4];
        t[k] = w.x * h.x + w.y * h.y + w.z * h.z + w.w * h.w;
    }
#pragma unroll
    for (int off = 16; off; off >>= 1) {
#pragma unroll
        for (int k = 0; k < 4; ++k)
            t[k] += __shfl_xor_sync(0xffffffff, t[k], off);
    }
    if (lane == 0) {
        g_t[0 * N_NODES + node] = t[0];
        g_t[1 * N_NODES + node] = t[1];
        g_t[2 * N_NODES + node] = t[2];
        g_t[3 * N_NODES + node] = t[3];
    }
}

// ------------------------------ scalar Horner propagation ------------------
__global__ void k_sprop(int phase, const float* __restrict__ bias2,
                        float* __restrict__ dout) {
    int n = blockIdx.x * blockDim.x + threadIdx.x;
    if (n >= N_NODES) return;
    const float* prev;
    const float* tk;
    if (phase == 0)      { prev = &g_t[3 * N_NODES]; tk = &g_t[2 * N_NODES]; }
    else if (phase == 1) { prev = &g_u[0];           tk = &g_t[1 * N_NODES]; }
    else                 { prev = &g_u[N_NODES];     tk = &g_t[0]; }

    float a = tk[n];
    int s = g_indptr[n], e = g_indptr[n + 1];
    float b = 0.f;
    int i = s;
    for (; i + 1 < e; i += 2) {
        a += __ldg(&g_ew[i])     * __ldg(&prev[__ldg(&g_src[i])]);
        b += __ldg(&g_ew[i + 1]) * __ldg(&prev[__ldg(&g_src[i + 1])]);
    }
    if (i < e) a += __ldg(&g_ew[i]) * __ldg(&prev[__ldg(&g_src[i])]);
    a += b;

    if (phase == 0)      g_u[n] = a;
    else if (phase == 1) g_u[N_NODES + n] = a;
    else                 dout[n] = a + bias2[0];
}

// ---------------------------------------------------------------------------
extern "C" void kernel_launch(void* const* d_in, const int* in_sizes, int n_in,
                              void* d_out, int out_size) {
    const float* x     = (const float*)d_in[0];
    const int*   ei    = (const int*)  d_in[1];
    const float* g1    = (const float*)d_in[2];
    const float* b1    = (const float*)d_in[3];
    const float* m1    = (const float*)d_in[4];
    const float* v1    = (const float*)d_in[5];
    const float* W1    = (const float*)d_in[6];
    const float* bias1 = (const float*)d_in[7];
    const float* g2    = (const float*)d_in[8];
    const float* b2    = (const float*)d_in[9];
    const float* m2    = (const float*)d_in[10];
    const float* v2    = (const float*)d_in[11];
    const float* W2    = (const float*)d_in[12];
    const float* bias2 = (const float*)d_in[13];
    const int* row = ei;
    const int* col = ei + N_EDGES;
    float* out = (float*)d_out;

    cudaFuncSetAttribute(k_gemm, cudaFuncAttributeMaxDynamicSharedMemorySize,
                         GEMM_SMEM_BYTES);

    const int TB = 256;
    // ---- CSR build ----
    k_zero <<<(N_NODES + TB - 1) / TB, TB>>>();
    k_count<<<(N_EDGES + TB - 1) / TB, TB>>>(col);
    k_dis  <<<(N_NODES + TB - 1) / TB, TB>>>();
    k_scan1<<<SCAN_NB, SCAN_B>>>();
    k_scan2<<<1, 256>>>();
    k_scan3<<<SCAN_NB, SCAN_B>>>();
    k_fill <<<(N_EDGES + TB - 1) / TB, TB>>>(row, col);

    // ---- weights + BN1 ----
    k_prepw<<<(DCAT * 32 + TB - 1) / TB, TB>>>(W1);
    k_bn1  <<<(N_NODES * DPAD + TB - 1) / TB, TB>>>(x, g1, b1, m1, v1);

    // ---- layer1: 3 propagation hops in 67-dim space ----
    int propGrid = (N_NODES * 32 + TB - 1) / TB;
    k_prop<<<propGrid, TB>>>(0 * DPAD, 1 * DPAD);
    k_prop<<<propGrid, TB>>>(1 * DPAD, 2 * DPAD);
    k_prop<<<propGrid, TB>>>(2 * DPAD, 3 * DPAD);

    // ---- layer1: fused projection GEMM ----
    k_gemm<<<(N_NODES + 63) / 64, 256, GEMM_SMEM_BYTES>>>(bias1);

    // ---- layer2: BN2 + leakyrelu + scalar projections ----
    k_bn2dot<<<(N_NODES * 32 + TB - 1) / TB, TB>>>(g2, b2, m2, v2, W2);

    // ---- layer2: Horner scalar propagation ----
    int ng = (N_NODES + TB - 1) / TB;
    k_sprop<<<ng, TB>>>(0, bias2, out);
    k_sprop<<<ng, TB>>>(1, bias2, out);
    k_sprop<<<ng, TB>>>(2, bias2, out);
}